// round 12
// baseline (speedup 1.0000x reference)
#include <cuda_runtime.h>
#include <cuda_bf16.h>
#include <math.h>

#define B      32
#define TIN    256
#define TOUT   512
#define NMEL   80
#define NBLK   128
#define NTHR   1024
#define DSF    32768                 /* 4 ring slots x 8192 floats = 128 KB */
#define DSBYTES (DSF * 4)

#define GATE_OFF  (B*NMEL*TOUT)
#define ALIGN_OFF (GATE_OFF + B*TOUT)

#define NKT_ATT 112      /* 1792 / 16 */
#define NKT_DEC 160      /* 2560 / 16 */

typedef unsigned long long ull;

// ---------------------------------------------------------------------------
// helpers
// ---------------------------------------------------------------------------
__device__ __forceinline__ float ftanh(float x) {
    float y;
    asm("tanh.approx.f32 %0, %1;" : "=f"(y) : "f"(x));
    return y;
}
__device__ __forceinline__ float fsig(float x) {
    return fmaf(ftanh(x * 0.5f), 0.5f, 0.5f);
}
__device__ __forceinline__ unsigned smem_u32(const void* p) {
    return (unsigned)__cvta_generic_to_shared(p);
}
__device__ __forceinline__ void fma2(ull &d, ull a, ull b) {
    asm("fma.rn.f32x2 %0, %1, %2, %3;" : "=l"(d) : "l"(a), "l"(b), "l"(d));
}
__device__ __forceinline__ float hsum(ull v) {
    float a, b;
    asm("mov.b64 {%0,%1}, %2;" : "=f"(a), "=f"(b) : "l"(v));
    return a + b;
}
__device__ __forceinline__ ull pk(unsigned lo, unsigned hi) {
    ull r;
    asm("mov.b64 %0, {%1,%2};" : "=l"(r) : "r"(lo), "r"(hi));
    return r;
}

__device__ __forceinline__ void mma_bf(float* d, unsigned a0, unsigned a1,
                                       unsigned a2, unsigned a3,
                                       unsigned b0, unsigned b1) {
    asm volatile(
        "mma.sync.aligned.m16n8k16.row.col.f32.bf16.bf16.f32 "
        "{%0,%1,%2,%3},{%4,%5,%6,%7},{%8,%9},{%0,%1,%2,%3};"
        : "+f"(d[0]), "+f"(d[1]), "+f"(d[2]), "+f"(d[3])
        : "r"(a0), "r"(a1), "r"(a2), "r"(a3), "r"(b0), "r"(b1));
}

// ---- TMA bulk copy + mbarrier ----
__device__ __forceinline__ void cpbulk(unsigned dst, const void* src,
                                       unsigned bytes, unsigned mbar) {
    asm volatile(
        "cp.async.bulk.shared::cta.global.mbarrier::complete_tx::bytes "
        "[%0], [%1], %2, [%3];"
        :: "r"(dst), "l"(src), "r"(bytes), "r"(mbar) : "memory");
}
__device__ __forceinline__ void mb_init(unsigned mbar, unsigned count) {
    asm volatile("mbarrier.init.shared.b64 [%0], %1;" :: "r"(mbar), "r"(count) : "memory");
}
__device__ __forceinline__ void mb_expect(unsigned mbar, unsigned bytes) {
    asm volatile("mbarrier.arrive.expect_tx.shared.b64 _, [%0], %1;"
                 :: "r"(mbar), "r"(bytes) : "memory");
}
__device__ __forceinline__ void mb_wait(unsigned mbar, unsigned parity) {
    unsigned done;
    asm volatile(
        "{\n\t.reg .pred p;\n\t"
        "mbarrier.try_wait.parity.acquire.cta.shared::cta.b64 p, [%1], %2;\n\t"
        "selp.b32 %0, 1, 0, p;\n\t}"
        : "=r"(done) : "r"(mbar), "r"(parity) : "memory");
    while (!done) {
        asm volatile(
            "{\n\t.reg .pred p;\n\t"
            "mbarrier.try_wait.parity.acquire.cta.shared::cta.b64 p, [%1], %2, 0x989680;\n\t"
            "selp.b32 %0, 1, 0, p;\n\t}"
            : "=r"(done) : "r"(mbar), "r"(parity) : "memory");
    }
}

// ---------------------------------------------------------------------------
// device-global state
// ---------------------------------------------------------------------------
// fragment-packed weights: [cta][kt][mt][lane][8 words: hi0..3, lo0..3]
__device__ __align__(16) unsigned g_attW[128 * NKT_ATT * 2 * 256];
__device__ __align__(16) unsigned g_decW[128 * NKT_DEC * 2 * 256];
// fragment-packed x buffers: per ktile: [4 nt][32 lane][4 words]
__device__ __align__(16) unsigned g_attP[TOUT * 16 * 512];     // prenet, per t
__device__ __align__(16) unsigned g_attCtx[32 * 512];
__device__ __align__(16) unsigned g_attAh[2][64 * 512];
__device__ __align__(16) unsigned g_decAh[64 * 512];
__device__ __align__(16) unsigned g_decCtx[32 * 512];
__device__ __align__(16) unsigned g_decDh[2][64 * 512];
// fp32 activations for scalar consumers [b][feature]
__device__ __align__(16) float g_ahF[B * 1024];
__device__ __align__(16) float g_dhF[B * 1024];
__device__ __align__(16) float g_ctxF[B * 512];
// cell states [u][b]
__device__ __align__(16) float g_ac[1024 * B];
__device__ __align__(16) float g_dc[1024 * B];
// attention
__device__ __align__(16) float g_pm[B * 128 * TIN];     // processed_memory [b][a][t]
__device__ __align__(16) float g_memT[B * 512 * TIN];   // memory [b][e][t]
__device__ float g_aw[B * TIN];
__device__ float g_awc[B * TIN];
__device__ float g_e[B * TIN];
__device__ float g_pq[B * 128];
__device__ volatile unsigned g_gen;
__device__ unsigned g_cnt;

// ---------------------------------------------------------------------------
// grid barrier (all 128 CTAs co-resident, 1/SM)
// ---------------------------------------------------------------------------
__device__ __forceinline__ void gbar(unsigned &gen) {
    gen++;
    __threadfence();
    __syncthreads();
    if (threadIdx.x == 0) {
        if (atomicAdd(&g_cnt, 1u) == NBLK - 1) {
            g_cnt = 0;
            __threadfence();
            g_gen = gen;
        } else {
            while (g_gen < gen) { }
        }
    }
    __syncthreads();
}

__global__ void k_reset() { g_gen = 0; g_cnt = 0; }

// ---------------------------------------------------------------------------
// x packer
// ---------------------------------------------------------------------------
__device__ __forceinline__ void pack_x(unsigned* base, int ktile, int kk, int n, float v) {
    int reg = (kk >> 3) & 1;
    int t4  = (kk & 7) >> 1;
    int hl  = kk & 1;
    int lane = (n & 7) * 4 + t4;
    int nt = n >> 3;
    unsigned short* p = (unsigned short*)(base + ((size_t)(ktile * 4 + nt) * 32 + lane) * 4 + reg) + hl;
    __nv_bfloat16 h = __float2bfloat16_rn(v);
    *p = __bfloat16_as_ushort(h);
    float lo = v - __bfloat162float(h);
    *(p + 4) = __bfloat16_as_ushort(__float2bfloat16_rn(lo));
}

// ---------------------------------------------------------------------------
// weight preprocessor -> [cta][kt][mt][lane][hi4|lo4]
// ---------------------------------------------------------------------------
__device__ void prep_W(unsigned* dst, const float* wih, const float* whh,
                       int NKT, int LIH, int cta, int tid) {
    int total = 2 * NKT * 32 * 4;
    for (int i = tid; i < total; i += NTHR) {
        int r = i & 3;
        int lane = (i >> 2) & 31;
        int ktm = i >> 7;
        int kt = ktm % NKT, mt = ktm / NKT;
        int g = lane >> 2, t4 = lane & 3;
        int rl = mt * 16 + g + (r & 1) * 8;
        int rg = (rl >> 3) * 1024 + cta * 8 + (rl & 7);
        int k = kt * 16 + (r & 2) * 4 + 2 * t4;
        const float* src = (k < LIH) ? (wih + (size_t)rg * LIH + k)
                                     : (whh + (size_t)rg * 1024 + (k - LIH));
        float w0 = src[0], w1 = src[1];
        __nv_bfloat16 h0 = __float2bfloat16_rn(w0), h1 = __float2bfloat16_rn(w1);
        float l0 = w0 - __bfloat162float(h0);
        float l1 = w1 - __bfloat162float(h1);
        unsigned hw = ((unsigned)__bfloat16_as_ushort(h1) << 16) | __bfloat16_as_ushort(h0);
        unsigned lw = ((unsigned)__bfloat16_as_ushort(__float2bfloat16_rn(l1)) << 16)
                    | __bfloat16_as_ushort(__float2bfloat16_rn(l0));
        size_t base = (((size_t)(cta * NKT + kt) * 2 + mt) * 32 + lane) * 8;
        dst[base + r] = hw;
        dst[base + 4 + r] = lw;
    }
}

// ---------------------------------------------------------------------------
// LSTM via MMA + TMA-bulk ring: 4 slots x 32 KB (A 16 KB | B 16 KB),
// stage = 8 ktiles, prefetch depth 3. ONE thread issues 2 bulk copies per
// stage; everyone else mbarrier-waits. Per-slot parity in `ph` (uniform).
// ---------------------------------------------------------------------------
__device__ __forceinline__ void lstm_mma(
    const unsigned* Wp, int NKT,
    const unsigned* B0, int n0, const unsigned* B1, int n1,
    const unsigned* B2, int n2,
    const float* __restrict__ bias,
    float* cst, float* hF, unsigned* packA, unsigned* packB,
    int cta, int tid, float* ds, float* s_red,
    unsigned &ph, unsigned mbar0) {

    const int wi = tid >> 5, lane = tid & 31;
    const int nh = wi >> 4, ks = (wi >> 1) & 7, mt = wi & 1;
    const int NSTG = NKT / 8;

    __syncthreads();                    // ds free from previous phase

    const char* Abase = (const char*)Wp + (size_t)cta * NKT * 2048;
    const unsigned dbase = smem_u32(ds);

#define LM_ISSUE(S) do {                                                    \
        if (tid == 0) {                                                     \
            int kb_ = (S) * 8;                                              \
            int slot_ = (S) & 3;                                            \
            unsigned mb_ = mbar0 + (unsigned)slot_ * 8u;                    \
            unsigned d_ = dbase + (unsigned)slot_ * 32768u;                 \
            mb_expect(mb_, 32768u);                                         \
            cpbulk(d_, Abase + (size_t)kb_ * 2048, 16384u, mb_);            \
            const char* sb_;                                                \
            if (kb_ < n0) sb_ = (const char*)B0 + (size_t)kb_ * 2048;       \
            else if (kb_ < n0 + n1) sb_ = (const char*)B1 + (size_t)(kb_ - n0) * 2048; \
            else sb_ = (const char*)B2 + (size_t)(kb_ - n0 - n1) * 2048;    \
            cpbulk(d_ + 16384u, sb_, 16384u, mb_);                          \
        }                                                                   \
    } while (0)

    LM_ISSUE(0);
    LM_ISSUE(1);
    LM_ISSUE(2);

    float acc[2][4];
#pragma unroll
    for (int i = 0; i < 2; i++)
#pragma unroll
        for (int j = 0; j < 4; j++) acc[i][j] = 0.f;

    for (int s = 0; s < NSTG; s++) {
        int slot = s & 3;
        mb_wait(mbar0 + (unsigned)slot * 8u, (ph >> slot) & 1u);
        ph ^= (1u << slot);

        const uint4* As = (const uint4*)(ds + slot * 8192);
        const uint4* Bs = As + 1024;
        uint4 Ah = As[((ks * 2 + mt) * 32 + lane) * 2];
        uint4 Al = As[((ks * 2 + mt) * 32 + lane) * 2 + 1];
#pragma unroll
        for (int j = 0; j < 2; j++) {
            int nt = nh * 2 + j;
            uint4 Bv = Bs[(ks * 4 + nt) * 32 + lane];
            mma_bf(acc[j], Ah.x, Ah.y, Ah.z, Ah.w, Bv.x, Bv.y);  // hi*hi
            mma_bf(acc[j], Ah.x, Ah.y, Ah.z, Ah.w, Bv.z, Bv.w);  // hi*lo
            mma_bf(acc[j], Al.x, Al.y, Al.z, Al.w, Bv.x, Bv.y);  // lo*hi
        }
        __syncthreads();                 // all reads of slot (s-1)&3 done
        if (s + 3 < NSTG) LM_ISSUE(s + 3);
    }
#undef LM_ISSUE

    // K-split partials -> slot-0 overlay (all copies consumed)
    float* red = ds;
    {
        int g = lane >> 2, t4 = lane & 3;
        int r0 = mt * 16 + g;
#pragma unroll
        for (int j = 0; j < 2; j++) {
            int nt = nh * 2 + j;
            int c0 = nt * 8 + t4 * 2;
            red[(ks * 32 + r0) * 32 + c0]         = acc[j][0];
            red[(ks * 32 + r0) * 32 + c0 + 1]     = acc[j][1];
            red[(ks * 32 + r0 + 8) * 32 + c0]     = acc[j][2];
            red[(ks * 32 + r0 + 8) * 32 + c0 + 1] = acc[j][3];
        }
    }
    __syncthreads();
    {
        int r = tid >> 5, b = lane;
        float s = bias[(r >> 3) * 1024 + cta * 8 + (r & 7)];
#pragma unroll
        for (int k2 = 0; k2 < 8; k2++) s += red[(k2 * 32 + r) * 32 + b];
        s_red[r * 32 + b] = s;
    }
    __syncthreads();
    if (tid < 256) {
        int uoff = tid >> 5, b = tid & 31;
        int u = cta * 8 + uoff;
        float gi = s_red[(uoff) * 32 + b];
        float gf = s_red[(8 + uoff) * 32 + b];
        float gg = s_red[(16 + uoff) * 32 + b];
        float go = s_red[(24 + uoff) * 32 + b];
        float c  = cst[u * 32 + b];
        float c2 = fsig(gf) * c + fsig(gi) * ftanh(gg);
        float h2 = fsig(go) * ftanh(c2);
        cst[u * 32 + b] = c2;
        hF[(size_t)b * 1024 + u] = h2;
        pack_x(packA, u >> 4, u & 15, b, h2);
        if (packB) pack_x(packB, u >> 4, u & 15, b, h2);
    }
}

// ---------------------------------------------------------------------------
// the persistent kernel
// ---------------------------------------------------------------------------
__global__ void __launch_bounds__(NTHR, 1) k_main(
    const float* __restrict__ memory, const float* __restrict__ dec_in,
    const int*   __restrict__ memlen,
    const float* __restrict__ prenet_w1, const float* __restrict__ prenet_w2,
    const float* __restrict__ att_wih, const float* __restrict__ att_whh,
    const float* __restrict__ att_b,
    const float* __restrict__ wq, const float* __restrict__ wm,
    const float* __restrict__ v,
    const float* __restrict__ loc_conv, const float* __restrict__ loc_dense,
    const float* __restrict__ dec_wih, const float* __restrict__ dec_whh,
    const float* __restrict__ dec_b,
    const float* __restrict__ proj_w, const float* __restrict__ proj_b,
    const float* __restrict__ gate_w, const float* __restrict__ gate_b,
    float* __restrict__ out) {

    extern __shared__ __align__(16) float ds[];    // 32768 floats (128 KB)
    __shared__ __align__(16) float s_red[1024];
    __shared__ __align__(16) float s_dense[4096];  // loc_dense [a][f]
    __shared__ float s_lc[1984];                   // loc_conv
    __shared__ __align__(8) ull s_mbar[4];

    const int cta = blockIdx.x;
    const int tid = threadIdx.x;
    const int wi = tid >> 5, lane = tid & 31;
    unsigned gen = 0;
    unsigned ph = 0;
    const unsigned mbar0 = smem_u32(&s_mbar[0]);

    if (tid == 0) {
#pragma unroll
        for (int i = 0; i < 4; i++) mb_init(mbar0 + i * 8u, 1u);
        asm volatile("fence.proxy.async.shared::cta;" ::: "memory");
    }
    for (int i = tid; i < 1984; i += NTHR) s_lc[i] = loc_conv[i];
    for (int i = tid; i < 4096; i += NTHR) s_dense[i] = loc_dense[i];
    __syncthreads();

    // ---- zero recurrent state + packed x buffers ----
    for (int i = cta * NTHR + tid; i < 1024 * B; i += NBLK * NTHR) {
        g_ac[i] = 0.f; g_dc[i] = 0.f;
        g_ahF[i] = 0.f; g_dhF[i] = 0.f;
    }
    for (int i = cta * NTHR + tid; i < 512 * B; i += NBLK * NTHR) g_ctxF[i] = 0.f;
    for (int i = cta * NTHR + tid; i < B * TIN; i += NBLK * NTHR) { g_aw[i] = 0.f; g_awc[i] = 0.f; }
    for (int i = cta * NTHR + tid; i < 64 * 512; i += NBLK * NTHR) {
        g_attAh[0][i] = 0u; g_attAh[1][i] = 0u;
        g_decAh[i] = 0u;
        g_decDh[0][i] = 0u; g_decDh[1][i] = 0u;
    }
    for (int i = cta * NTHR + tid; i < 32 * 512; i += NBLK * NTHR) {
        g_attCtx[i] = 0u; g_decCtx[i] = 0u;
    }

    // ---- pack weights (own slice) ----
    prep_W(g_attW, att_wih, att_whh, NKT_ATT, 768, cta, tid);
    prep_W(g_decW, dec_wih, dec_whh, NKT_DEC, 1536, cta, tid);

    // ---- prenet for all 512 steps (32 rounds x 4 groups of 256 threads) ----
    {
        int grp = tid >> 8, sub = tid & 255;
        float* sd = ds + grp * 512;
        float* sx = sd + 96;
        for (int r = 0; r < 32; r++) {
            int job = r * 512 + cta * 4 + grp;
            int t = job >> 5, b = job & 31;
            __syncthreads();
            if (sub < 80)
                sd[sub] = (t == 0) ? 0.f : dec_in[(size_t)b * NMEL * TOUT + sub * TOUT + (t - 1)];
            __syncthreads();
            float s = 0.f;
            const float* w = prenet_w1 + sub * 80;
#pragma unroll 8
            for (int m = 0; m < 80; m++) s += w[m] * sd[m];
            sx[sub] = fmaxf(s, 0.f);
            __syncthreads();
            s = 0.f;
            const float* w2 = prenet_w2 + sub * 256;
#pragma unroll 8
            for (int m = 0; m < 256; m++) s += w2[m] * sx[m];
            s = fmaxf(s, 0.f);
            pack_x(g_attP + (size_t)t * 8192, sub >> 4, sub & 15, b, s);
        }
    }

    // ---- processed_memory + memory transpose (8 rounds x 8 groups of 128) ----
    {
        int grp = tid >> 7, sub = tid & 127;
        float* sm = ds + 8192 + grp * 512;
        for (int r = 0; r < 8; r++) {
            int job = r * 1024 + cta * 8 + grp;
            int tt = job >> 5, b = job & 31;
            __syncthreads();
            for (int e = sub; e < 512; e += 128) {
                float vv = memory[((size_t)b * TIN + tt) * 512 + e];
                sm[e] = vv;
                g_memT[((size_t)b * 512 + e) * TIN + tt] = vv;
            }
            __syncthreads();
            float s = 0.f;
            const float* w = wm + sub * 512;
#pragma unroll 8
            for (int e = 0; e < 512; e++) s += w[e] * sm[e];
            g_pm[((size_t)b * 128 + sub) * TIN + tt] = s;
        }
    }

    gbar(gen);

    // ======================= main recurrence =======================
    for (int t = 0; t < TOUT; t++) {
        int p = t & 1;

        // ---- P1: attention LSTM ----
        lstm_mma(g_attW, NKT_ATT,
                 g_attP + (size_t)t * 8192, 16,
                 g_attCtx, 32,
                 g_attAh[p], 64,
                 att_b, g_ac, g_ahF, g_attAh[p ^ 1], g_decAh,
                 cta, tid, ds, s_red, ph, mbar0);
        gbar(gen);

        // ---- P2: pq = ah @ wq^T (a = cta, warp = batch) ----
        {
            int b = wi;
            float s = 0.f;
            const float* wr = wq + (size_t)cta * 1024;
            const float* hv = g_ahF + (size_t)b * 1024;
#pragma unroll 8
            for (int j = 0; j < 32; j++) {
                int f = lane + 32 * j;
                s += wr[f] * hv[f];
            }
#pragma unroll
            for (int o = 16; o; o >>= 1) s += __shfl_down_sync(0xffffffffu, s, o);
            if (lane == 0) g_pq[b * 128 + cta] = s;
        }
        gbar(gen);

        // ---- P3: energies (2 tiles per CTA; skip fully-masked tiles) ----
        {
            int ts = tid >> 9, sub = tid & 511;
            int tile = cta * 2 + ts;            // (b, t-tile)
            int b = tile >> 3;
            int t0 = (tile & 7) * 32;
            bool active = (t0 < memlen[b]);
            float* scr  = ds + ts * 2048;
            float* cat  = scr;                  // [2][64]
            float* co   = scr + 128;            // [32][36] padded
            float* spq  = scr + 1280;           // [128]
            float* part = scr + 1408;           // [16][32]
            if (active) {
                if (sub < 124) {
                    int c = sub / 62, tl = sub % 62;
                    int tg = t0 - 15 + tl;
                    float vv = 0.f;
                    if (tg >= 0 && tg < TIN) vv = (c ? g_awc : g_aw)[b * TIN + tg];
                    cat[c * 64 + tl] = vv;
                }
                if (sub < 128) spq[sub] = g_pq[b * 128 + sub];
            }
            __syncthreads();
            if (active) {
#pragma unroll
                for (int j = 0; j < 2; j++) {
                    int id = sub + j * 512;
                    int tl = id >> 5, f = id & 31;
                    const float* lc = &s_lc[f * 62];
                    float s = 0.f;
#pragma unroll
                    for (int k = 0; k < 31; k++) s += lc[k] * cat[tl + k];
#pragma unroll
                    for (int k = 0; k < 31; k++) s += lc[31 + k] * cat[64 + tl + k];
                    co[tl * 36 + f] = s;
                }
            }
            __syncthreads();
            if (active) {
                int wa = sub >> 5, tl = sub & 31;
                uint4 cr[8];
                const uint4* co4 = (const uint4*)(co + tl * 36);
#pragma unroll
                for (int k = 0; k < 8; k++) cr[k] = co4[k];
                const float* pmb = g_pm + ((size_t)b * 128) * TIN + t0 + tl;
                float accv = 0.f;
#pragma unroll 2
                for (int a = wa * 8; a < wa * 8 + 8; a++) {
                    const uint4* d4 = (const uint4*)&s_dense[a * 32];
                    ull p0 = 0, p1 = 0;
#pragma unroll
                    for (int k = 0; k < 8; k++) {
                        uint4 dv = d4[k];
                        fma2(p0, pk(dv.x, dv.y), pk(cr[k].x, cr[k].y));
                        fma2(p1, pk(dv.z, dv.w), pk(cr[k].z, cr[k].w));
                    }
                    float loc = hsum(p0) + hsum(p1);
                    float pmv = pmb[(size_t)a * TIN];
                    accv += ftanh(spq[a] + pmv + loc) * __ldg(v + a);
                }
                part[wa * 32 + tl] = accv;
            }
            __syncthreads();
            if (sub < 32) {
                int tg = t0 + sub;
                float e = -1e9f;
                if (active && tg < memlen[b]) {
                    e = 0.f;
#pragma unroll
                    for (int j = 0; j < 16; j++) e += part[j * 32 + sub];
                }
                g_e[b * TIN + tg] = e;
            }
        }
        gbar(gen);

        // ---- P4: softmax + context (CTA -> (b, e-quarter)) ----
        {
            int b = cta >> 2, x = cta & 3;
            float* s_wgt = ds;
            float* red   = ds + 256;
            float* bval  = ds + 266;
            float e = (tid < 256) ? g_e[b * 256 + tid] : -1e30f;
            float m = e;
#pragma unroll
            for (int o = 16; o; o >>= 1) m = fmaxf(m, __shfl_xor_sync(0xffffffffu, m, o));
            if (lane == 0 && tid < 256) red[wi] = m;
            __syncthreads();
            if (tid == 0) {
                float mm = red[0];
#pragma unroll
                for (int i = 1; i < 8; i++) mm = fmaxf(mm, red[i]);
                bval[0] = mm;
            }
            __syncthreads();
            float w0 = (tid < 256) ? __expf(e - bval[0]) : 0.f;
            float ssum = w0;
#pragma unroll
            for (int o = 16; o; o >>= 1) ssum += __shfl_xor_sync(0xffffffffu, ssum, o);
            if (lane == 0 && tid < 256) red[wi] = ssum;
            __syncthreads();
            if (tid == 0) {
                float tt2 = 0.f;
#pragma unroll
                for (int i = 0; i < 8; i++) tt2 += red[i];
                bval[1] = tt2;
            }
            __syncthreads();
            if (tid < 256) {
                float wgt = w0 * __fdividef(1.f, bval[1]);
                s_wgt[tid] = wgt;
                if (x == 0) {
                    g_aw[b * 256 + tid] = wgt;
                    g_awc[b * 256 + tid] += wgt;
                    out[ALIGN_OFF + (size_t)(b * TOUT + t) * TIN + tid] = wgt;
                }
            }
            __syncthreads();
            {
                int ebase = x * 128 + wi * 4;
#pragma unroll
                for (int i = 0; i < 4; i++) {
                    int e2 = ebase + i;
                    const float* mrow = g_memT + ((size_t)b * 512 + e2) * TIN;
                    float s = 0.f;
#pragma unroll
                    for (int j = 0; j < 8; j++) {
                        int tt3 = lane + 32 * j;
                        s += mrow[tt3] * s_wgt[tt3];
                    }
#pragma unroll
                    for (int o = 16; o; o >>= 1) s += __shfl_down_sync(0xffffffffu, s, o);
                    if (lane == 0) {
                        g_ctxF[(size_t)b * 512 + e2] = s;
                        pack_x(g_attCtx, e2 >> 4, e2 & 15, b, s);
                        pack_x(g_decCtx, e2 >> 4, e2 & 15, b, s);
                    }
                }
            }
        }
        gbar(gen);

        // ---- P5: decoder LSTM ----
        lstm_mma(g_decW, NKT_DEC,
                 g_decAh, 64,
                 g_decCtx, 32,
                 g_decDh[p], 64,
                 dec_b, g_dc, g_dhF, g_decDh[p ^ 1], (unsigned*)0,
                 cta, tid, ds, s_red, ph, mbar0);
        gbar(gen);

        // ---- P6: projection + gate (CTAs 0..80; o = cta, warp = batch) ----
        if (cta < 81) {
            int b = wi;
            float s = 0.f;
            const float* wrow = (cta < 80) ? (proj_w + (size_t)cta * 1536) : gate_w;
            const float* dv = g_dhF + (size_t)b * 1024;
            const float* cv = g_ctxF + (size_t)b * 512;
#pragma unroll 8
            for (int j = 0; j < 48; j++) {
                int f = lane + 32 * j;
                float xv = (f < 1024) ? dv[f] : cv[f - 1024];
                s += wrow[f] * xv;
            }
#pragma unroll
            for (int o = 16; o; o >>= 1) s += __shfl_down_sync(0xffffffffu, s, o);
            if (lane == 0) {
                if (cta < 80)
                    out[((size_t)b * NMEL + cta) * TOUT + t] = s + proj_b[cta];
                else
                    out[GATE_OFF + (size_t)b * TOUT + t] = s + gate_b[0];
            }
        }
    }
}

// ---------------------------------------------------------------------------
// launch: 2 graph nodes
// ---------------------------------------------------------------------------
extern "C" void kernel_launch(void* const* d_in, const int* in_sizes, int n_in,
                              void* d_out, int out_size) {
    const float* memory    = (const float*)d_in[0];
    const float* dec_in    = (const float*)d_in[1];
    const int*   memlen    = (const int*)  d_in[2];
    const float* prenet_w1 = (const float*)d_in[3];
    const float* prenet_w2 = (const float*)d_in[4];
    const float* att_wih   = (const float*)d_in[5];
    const float* att_whh   = (const float*)d_in[6];
    const float* att_b     = (const float*)d_in[7];
    const float* wq        = (const float*)d_in[8];
    const float* wm        = (const float*)d_in[9];
    const float* v         = (const float*)d_in[10];
    const float* loc_conv  = (const float*)d_in[11];
    const float* loc_dense = (const float*)d_in[12];
    const float* dec_wih   = (const float*)d_in[13];
    const float* dec_whh   = (const float*)d_in[14];
    const float* dec_b     = (const float*)d_in[15];
    const float* proj_w    = (const float*)d_in[16];
    const float* proj_b    = (const float*)d_in[17];
    const float* gate_w    = (const float*)d_in[18];
    const float* gate_b    = (const float*)d_in[19];
    float* out = (float*)d_out;

    cudaFuncSetAttribute(k_main, cudaFuncAttributeMaxDynamicSharedMemorySize, DSBYTES);

    k_reset<<<1, 32>>>();
    k_main<<<NBLK, NTHR, DSBYTES>>>(memory, dec_in, memlen, prenet_w1, prenet_w2,
                                    att_wih, att_whh, att_b, wq, wm, v,
                                    loc_conv, loc_dense, dec_wih, dec_whh, dec_b,
                                    proj_w, proj_b, gate_w, gate_b, out);
}

// round 16
// speedup vs baseline: 1.0684x; 1.0684x over previous
#include <cuda_runtime.h>
#include <cuda_bf16.h>
#include <math.h>

#define B      32
#define TIN    256
#define TOUT   512
#define NMEL   80
#define NBLK   128
#define NTHR   1024
#define DSF    32768                 /* 4 ring slots x 8192 floats = 128 KB */
#define DSBYTES (DSF * 4)

#define GATE_OFF  (B*NMEL*TOUT)
#define ALIGN_OFF (GATE_OFF + B*TOUT)

#define NKT_ATT 112      /* 1792 / 16 */
#define NKT_DEC 160      /* 2560 / 16 */

typedef unsigned long long ull;

// ---------------------------------------------------------------------------
// helpers
// ---------------------------------------------------------------------------
__device__ __forceinline__ float ftanh(float x) {
    float y;
    asm("tanh.approx.f32 %0, %1;" : "=f"(y) : "f"(x));
    return y;
}
__device__ __forceinline__ float fsig(float x) {
    return fmaf(ftanh(x * 0.5f), 0.5f, 0.5f);
}
__device__ __forceinline__ unsigned smem_u32(const void* p) {
    return (unsigned)__cvta_generic_to_shared(p);
}
__device__ __forceinline__ void fma2(ull &d, ull a, ull b) {
    asm("fma.rn.f32x2 %0, %1, %2, %3;" : "=l"(d) : "l"(a), "l"(b), "l"(d));
}
__device__ __forceinline__ float hsum(ull v) {
    float a, b;
    asm("mov.b64 {%0,%1}, %2;" : "=f"(a), "=f"(b) : "l"(v));
    return a + b;
}
__device__ __forceinline__ ull pk(unsigned lo, unsigned hi) {
    ull r;
    asm("mov.b64 %0, {%1,%2};" : "=l"(r) : "r"(lo), "r"(hi));
    return r;
}
__device__ __forceinline__ void npause() {
    asm volatile("nanosleep.u32 64;");
}

__device__ __forceinline__ void mma_bf(float* d, unsigned a0, unsigned a1,
                                       unsigned a2, unsigned a3,
                                       unsigned b0, unsigned b1) {
    asm volatile(
        "mma.sync.aligned.m16n8k16.row.col.f32.bf16.bf16.f32 "
        "{%0,%1,%2,%3},{%4,%5,%6,%7},{%8,%9},{%0,%1,%2,%3};"
        : "+f"(d[0]), "+f"(d[1]), "+f"(d[2]), "+f"(d[3])
        : "r"(a0), "r"(a1), "r"(a2), "r"(a3), "r"(b0), "r"(b1));
}

// ---- TMA bulk copy + mbarrier ----
__device__ __forceinline__ void cpbulk(unsigned dst, const void* src,
                                       unsigned bytes, unsigned mbar) {
    asm volatile(
        "cp.async.bulk.shared::cta.global.mbarrier::complete_tx::bytes "
        "[%0], [%1], %2, [%3];"
        :: "r"(dst), "l"(src), "r"(bytes), "r"(mbar) : "memory");
}
__device__ __forceinline__ void cpbulk_pol(unsigned dst, const void* src,
                                           unsigned bytes, unsigned mbar, ull pol) {
    asm volatile(
        "cp.async.bulk.shared::cta.global.mbarrier::complete_tx::bytes.L2::cache_hint "
        "[%0], [%1], %2, [%3], %4;"
        :: "r"(dst), "l"(src), "r"(bytes), "r"(mbar), "l"(pol) : "memory");
}
__device__ __forceinline__ void mb_init(unsigned mbar, unsigned count) {
    asm volatile("mbarrier.init.shared.b64 [%0], %1;" :: "r"(mbar), "r"(count) : "memory");
}
__device__ __forceinline__ void mb_expect(unsigned mbar, unsigned bytes) {
    asm volatile("mbarrier.arrive.expect_tx.shared.b64 _, [%0], %1;"
                 :: "r"(mbar), "r"(bytes) : "memory");
}
__device__ __forceinline__ void mb_wait(unsigned mbar, unsigned parity) {
    unsigned done;
    asm volatile(
        "{\n\t.reg .pred p;\n\t"
        "mbarrier.try_wait.parity.acquire.cta.shared::cta.b64 p, [%1], %2;\n\t"
        "selp.b32 %0, 1, 0, p;\n\t}"
        : "=r"(done) : "r"(mbar), "r"(parity) : "memory");
    while (!done) {
        asm volatile(
            "{\n\t.reg .pred p;\n\t"
            "mbarrier.try_wait.parity.acquire.cta.shared::cta.b64 p, [%1], %2, 0x989680;\n\t"
            "selp.b32 %0, 1, 0, p;\n\t}"
            : "=r"(done) : "r"(mbar), "r"(parity) : "memory");
    }
}

// ---------------------------------------------------------------------------
// device-global state
// ---------------------------------------------------------------------------
// fragment-packed weights: [cta][kt][mt][lane][8 words: hi0..3, lo0..3]
__device__ __align__(16) unsigned g_attW[128 * NKT_ATT * 2 * 256];
__device__ __align__(16) unsigned g_decW[128 * NKT_DEC * 2 * 256];
// fragment-packed x buffers: per ktile: [4 nt][32 lane][4 words]
__device__ __align__(16) unsigned g_attP[TOUT * 16 * 512];     // prenet, per t
__device__ __align__(16) unsigned g_attCtx[32 * 512];
__device__ __align__(16) unsigned g_attAh[2][64 * 512];
__device__ __align__(16) unsigned g_decAh[2][64 * 512];        // double buffered
__device__ __align__(16) unsigned g_decCtx[32 * 512];
__device__ __align__(16) unsigned g_decDh[2][64 * 512];
// fp32 activations for scalar consumers [b][feature]
__device__ __align__(16) float g_ahF[B * 1024];
__device__ __align__(16) float g_dhF[B * 1024];
__device__ __align__(16) float g_ctxF[B * 512];
// cell states [u][b]
__device__ __align__(16) float g_ac[1024 * B];
__device__ __align__(16) float g_dc[1024 * B];
// attention
__device__ __align__(16) float g_pm[B * 128 * TIN];     // processed_memory [b][a][t]
__device__ __align__(16) float g_memT[B * 512 * TIN];   // memory [b][e][t]
__device__ float g_aw[B * TIN];
__device__ float g_awc[B * TIN];
__device__ float g_e[B * TIN];
__device__ float g_pq[B * 128];
__device__ volatile unsigned g_flags[NBLK * 32];        // padded barrier flags

// ---------------------------------------------------------------------------
// grid barrier: atomic-free, per-CTA padded flags + parallel poll (with
// nanosleep backoff so spinners don't hammer L2)
// ---------------------------------------------------------------------------
__device__ __forceinline__ void gbar(unsigned &gen, int cta, int tid) {
    gen++;
    __syncthreads();
    if (tid == 0) {
        __threadfence();
        g_flags[cta * 32] = gen;
    }
    if (tid < NBLK) {
        if (g_flags[tid * 32] < gen) {
            do { npause(); } while (g_flags[tid * 32] < gen);
        }
    }
    __syncthreads();
}

__global__ void k_reset() { g_flags[threadIdx.x * 32] = 0; }

// ---------------------------------------------------------------------------
// x packer
// ---------------------------------------------------------------------------
__device__ __forceinline__ void pack_x(unsigned* base, int ktile, int kk, int n, float v) {
    int reg = (kk >> 3) & 1;
    int t4  = (kk & 7) >> 1;
    int hl  = kk & 1;
    int lane = (n & 7) * 4 + t4;
    int nt = n >> 3;
    unsigned short* p = (unsigned short*)(base + ((size_t)(ktile * 4 + nt) * 32 + lane) * 4 + reg) + hl;
    __nv_bfloat16 h = __float2bfloat16_rn(v);
    *p = __bfloat16_as_ushort(h);
    float lo = v - __bfloat162float(h);
    *(p + 4) = __bfloat16_as_ushort(__float2bfloat16_rn(lo));
}

// ---------------------------------------------------------------------------
// weight preprocessor -> [cta][kt][mt][lane][hi4|lo4]
// ---------------------------------------------------------------------------
__device__ void prep_W(unsigned* dst, const float* wih, const float* whh,
                       int NKT, int LIH, int cta, int tid) {
    int total = 2 * NKT * 32 * 4;
    for (int i = tid; i < total; i += NTHR) {
        int r = i & 3;
        int lane = (i >> 2) & 31;
        int ktm = i >> 7;
        int kt = ktm % NKT, mt = ktm / NKT;
        int g = lane >> 2, t4 = lane & 3;
        int rl = mt * 16 + g + (r & 1) * 8;
        int rg = (rl >> 3) * 1024 + cta * 8 + (rl & 7);
        int k = kt * 16 + (r & 2) * 4 + 2 * t4;
        const float* src = (k < LIH) ? (wih + (size_t)rg * LIH + k)
                                     : (whh + (size_t)rg * 1024 + (k - LIH));
        float w0 = src[0], w1 = src[1];
        __nv_bfloat16 h0 = __float2bfloat16_rn(w0), h1 = __float2bfloat16_rn(w1);
        float l0 = w0 - __bfloat162float(h0);
        float l1 = w1 - __bfloat162float(h1);
        unsigned hw = ((unsigned)__bfloat16_as_ushort(h1) << 16) | __bfloat16_as_ushort(h0);
        unsigned lw = ((unsigned)__bfloat16_as_ushort(__float2bfloat16_rn(l1)) << 16)
                    | __bfloat16_as_ushort(__float2bfloat16_rn(l0));
        size_t base = (((size_t)(cta * NKT + kt) * 2 + mt) * 32 + lane) * 8;
        dst[base + r] = hw;
        dst[base + 4 + r] = lw;
    }
}

// ---------------------------------------------------------------------------
// LSTM via MMA + TMA-bulk ring (4 slots x 32 KB, depth 3).
// Weight copies carry L2::evict_last policy (pin weight set in L2).
// ---------------------------------------------------------------------------
__device__ __forceinline__ void lstm_mma(
    const unsigned* Wp, int NKT,
    const unsigned* B0, int n0, const unsigned* B1, int n1,
    const unsigned* B2, int n2,
    const float* __restrict__ bias,
    float* cst, float* hF, unsigned* packA, unsigned* packB,
    int cta, int tid, float* ds, float* s_red,
    unsigned &ph, unsigned mbar0, ull pol) {

    const int wi = tid >> 5, lane = tid & 31;
    const int nh = wi >> 4, ks = (wi >> 1) & 7, mt = wi & 1;
    const int NSTG = NKT / 8;

    __syncthreads();                    // ds free from previous phase

    const char* Abase = (const char*)Wp + (size_t)cta * NKT * 2048;
    const unsigned dbase = smem_u32(ds);

#define LM_ISSUE(S) do {                                                    \
        if (tid == 0) {                                                     \
            int kb_ = (S) * 8;                                              \
            int slot_ = (S) & 3;                                            \
            unsigned mb_ = mbar0 + (unsigned)slot_ * 8u;                    \
            unsigned d_ = dbase + (unsigned)slot_ * 32768u;                 \
            mb_expect(mb_, 32768u);                                         \
            cpbulk_pol(d_, Abase + (size_t)kb_ * 2048, 16384u, mb_, pol);   \
            const char* sb_;                                                \
            if (kb_ < n0) sb_ = (const char*)B0 + (size_t)kb_ * 2048;       \
            else if (kb_ < n0 + n1) sb_ = (const char*)B1 + (size_t)(kb_ - n0) * 2048; \
            else sb_ = (const char*)B2 + (size_t)(kb_ - n0 - n1) * 2048;    \
            cpbulk(d_ + 16384u, sb_, 16384u, mb_);                          \
        }                                                                   \
    } while (0)

    LM_ISSUE(0);
    LM_ISSUE(1);
    LM_ISSUE(2);

    float acc[2][4];
#pragma unroll
    for (int i = 0; i < 2; i++)
#pragma unroll
        for (int j = 0; j < 4; j++) acc[i][j] = 0.f;

    for (int s = 0; s < NSTG; s++) {
        int slot = s & 3;
        mb_wait(mbar0 + (unsigned)slot * 8u, (ph >> slot) & 1u);
        ph ^= (1u << slot);

        const uint4* As = (const uint4*)(ds + slot * 8192);
        const uint4* Bs = As + 1024;
        uint4 Ah = As[((ks * 2 + mt) * 32 + lane) * 2];
        uint4 Al = As[((ks * 2 + mt) * 32 + lane) * 2 + 1];
#pragma unroll
        for (int j = 0; j < 2; j++) {
            int nt = nh * 2 + j;
            uint4 Bv = Bs[(ks * 4 + nt) * 32 + lane];
            mma_bf(acc[j], Ah.x, Ah.y, Ah.z, Ah.w, Bv.x, Bv.y);  // hi*hi
            mma_bf(acc[j], Ah.x, Ah.y, Ah.z, Ah.w, Bv.z, Bv.w);  // hi*lo
            mma_bf(acc[j], Al.x, Al.y, Al.z, Al.w, Bv.x, Bv.y);  // lo*hi
        }
        __syncthreads();                 // all reads of slot done
        if (s + 3 < NSTG) LM_ISSUE(s + 3);
    }
#undef LM_ISSUE

    // K-split partials -> slot-0 overlay (all copies consumed)
    float* red = ds;
    {
        int g = lane >> 2, t4 = lane & 3;
        int r0 = mt * 16 + g;
#pragma unroll
        for (int j = 0; j < 2; j++) {
            int nt = nh * 2 + j;
            int c0 = nt * 8 + t4 * 2;
            red[(ks * 32 + r0) * 32 + c0]         = acc[j][0];
            red[(ks * 32 + r0) * 32 + c0 + 1]     = acc[j][1];
            red[(ks * 32 + r0 + 8) * 32 + c0]     = acc[j][2];
            red[(ks * 32 + r0 + 8) * 32 + c0 + 1] = acc[j][3];
        }
    }
    __syncthreads();
    {
        int r = tid >> 5, b = lane;
        float s = bias[(r >> 3) * 1024 + cta * 8 + (r & 7)];
#pragma unroll
        for (int k2 = 0; k2 < 8; k2++) s += red[(k2 * 32 + r) * 32 + b];
        s_red[r * 32 + b] = s;
    }
    __syncthreads();
    if (tid < 256) {
        int uoff = tid >> 5, b = tid & 31;
        int u = cta * 8 + uoff;
        float gi = s_red[(uoff) * 32 + b];
        float gf = s_red[(8 + uoff) * 32 + b];
        float gg = s_red[(16 + uoff) * 32 + b];
        float go = s_red[(24 + uoff) * 32 + b];
        float c  = cst[u * 32 + b];
        float c2 = fsig(gf) * c + fsig(gi) * ftanh(gg);
        float h2 = fsig(go) * ftanh(c2);
        cst[u * 32 + b] = c2;
        hF[(size_t)b * 1024 + u] = h2;
        pack_x(packA, u >> 4, u & 15, b, h2);
        if (packB) pack_x(packB, u >> 4, u & 15, b, h2);
    }
}

// ---------------------------------------------------------------------------
// the persistent kernel
// ---------------------------------------------------------------------------
__global__ void __launch_bounds__(NTHR, 1) k_main(
    const float* __restrict__ memory, const float* __restrict__ dec_in,
    const int*   __restrict__ memlen,
    const float* __restrict__ prenet_w1, const float* __restrict__ prenet_w2,
    const float* __restrict__ att_wih, const float* __restrict__ att_whh,
    const float* __restrict__ att_b,
    const float* __restrict__ wq, const float* __restrict__ wm,
    const float* __restrict__ v,
    const float* __restrict__ loc_conv, const float* __restrict__ loc_dense,
    const float* __restrict__ dec_wih, const float* __restrict__ dec_whh,
    const float* __restrict__ dec_b,
    const float* __restrict__ proj_w, const float* __restrict__ proj_b,
    const float* __restrict__ gate_w, const float* __restrict__ gate_b,
    float* __restrict__ out) {

    extern __shared__ __align__(16) float ds[];    // 32768 floats (128 KB)
    __shared__ __align__(16) float s_red[1024];
    __shared__ __align__(16) float s_dense[4096];  // loc_dense [a][f]
    __shared__ float s_lc[1984];                   // loc_conv
    __shared__ __align__(8) ull s_mbar[4];

    const int cta = blockIdx.x;
    const int tid = threadIdx.x;
    const int wi = tid >> 5, lane = tid & 31;
    unsigned gen = 0;
    unsigned ph = 0;
    const unsigned mbar0 = smem_u32(&s_mbar[0]);
    ull pol;
    asm("createpolicy.fractional.L2::evict_last.b64 %0, 1.0;" : "=l"(pol));

    if (tid == 0) {
#pragma unroll
        for (int i = 0; i < 4; i++) mb_init(mbar0 + i * 8u, 1u);
        asm volatile("fence.proxy.async.shared::cta;" ::: "memory");
    }
    for (int i = tid; i < 1984; i += NTHR) s_lc[i] = loc_conv[i];
    for (int i = tid; i < 4096; i += NTHR) s_dense[i] = loc_dense[i];
    __syncthreads();

    // ---- zero recurrent state + packed x buffers ----
    for (int i = cta * NTHR + tid; i < 1024 * B; i += NBLK * NTHR) {
        g_ac[i] = 0.f; g_dc[i] = 0.f;
        g_ahF[i] = 0.f; g_dhF[i] = 0.f;
    }
    for (int i = cta * NTHR + tid; i < 512 * B; i += NBLK * NTHR) g_ctxF[i] = 0.f;
    for (int i = cta * NTHR + tid; i < B * TIN; i += NBLK * NTHR) { g_aw[i] = 0.f; g_awc[i] = 0.f; }
    for (int i = cta * NTHR + tid; i < 64 * 512; i += NBLK * NTHR) {
        g_attAh[0][i] = 0u; g_attAh[1][i] = 0u;
        g_decAh[0][i] = 0u; g_decAh[1][i] = 0u;
        g_decDh[0][i] = 0u; g_decDh[1][i] = 0u;
    }
    for (int i = cta * NTHR + tid; i < 32 * 512; i += NBLK * NTHR) {
        g_attCtx[i] = 0u; g_decCtx[i] = 0u;
    }

    // ---- pack weights (own slice) ----
    prep_W(g_attW, att_wih, att_whh, NKT_ATT, 768, cta, tid);
    prep_W(g_decW, dec_wih, dec_whh, NKT_DEC, 1536, cta, tid);

    // ---- prenet for all 512 steps (32 rounds x 4 groups of 256 threads) ----
    {
        int grp = tid >> 8, sub = tid & 255;
        float* sd = ds + grp * 512;
        float* sx = sd + 96;
        for (int r = 0; r < 32; r++) {
            int job = r * 512 + cta * 4 + grp;
            int t = job >> 5, b = job & 31;
            __syncthreads();
            if (sub < 80)
                sd[sub] = (t == 0) ? 0.f : dec_in[(size_t)b * NMEL * TOUT + sub * TOUT + (t - 1)];
            __syncthreads();
            float s = 0.f;
            const float* w = prenet_w1 + sub * 80;
#pragma unroll 8
            for (int m = 0; m < 80; m++) s += w[m] * sd[m];
            sx[sub] = fmaxf(s, 0.f);
            __syncthreads();
            s = 0.f;
            const float* w2 = prenet_w2 + sub * 256;
#pragma unroll 8
            for (int m = 0; m < 256; m++) s += w2[m] * sx[m];
            s = fmaxf(s, 0.f);
            pack_x(g_attP + (size_t)t * 8192, sub >> 4, sub & 15, b, s);
        }
    }

    // ---- processed_memory + memory transpose (8 rounds x 8 groups of 128) ----
    {
        int grp = tid >> 7, sub = tid & 127;
        float* sm = ds + 8192 + grp * 512;
        for (int r = 0; r < 8; r++) {
            int job = r * 1024 + cta * 8 + grp;
            int tt = job >> 5, b = job & 31;
            __syncthreads();
            for (int e = sub; e < 512; e += 128) {
                float vv = memory[((size_t)b * TIN + tt) * 512 + e];
                sm[e] = vv;
                g_memT[((size_t)b * 512 + e) * TIN + tt] = vv;
            }
            __syncthreads();
            float s = 0.f;
            const float* w = wm + sub * 512;
#pragma unroll 8
            for (int e = 0; e < 512; e++) s += w[e] * sm[e];
            g_pm[((size_t)b * 128 + sub) * TIN + tt] = s;
        }
    }

    gbar(gen, cta, tid);

    // ======================= main recurrence (pipelined) =======================
    // iter t: [P5(t-1) | P1(t)] -> gbar -> [P2(t) | P6(t-1)] -> gbar
    //         -> P3(t) -> gbar -> P4(t) -> gbar     (C/D only if t < TOUT)
    for (int t = 0; t <= TOUT; t++) {

        // ---- Phase A ----
        if (t > 0) {
            int pd = (t - 1) & 1;
            lstm_mma(g_decW, NKT_DEC,
                     g_decAh[t & 1], 64, g_decCtx, 32, g_decDh[pd], 64,
                     dec_b, g_dc, g_dhF, g_decDh[pd ^ 1], (unsigned*)0,
                     cta, tid, ds, s_red, ph, mbar0, pol);
        }
        if (t < TOUT) {
            int pa = t & 1;
            lstm_mma(g_attW, NKT_ATT,
                     g_attP + (size_t)t * 8192, 16, g_attCtx, 32, g_attAh[pa], 64,
                     att_b, g_ac, g_ahF, g_attAh[pa ^ 1], g_decAh[pa ^ 1],
                     cta, tid, ds, s_red, ph, mbar0, pol);
        }
        gbar(gen, cta, tid);

        // ---- Phase B: P2(t) + P6(t-1) ----
        if (t < TOUT) {
            int b = wi;
            float s = 0.f;
            const float* wr = wq + (size_t)cta * 1024;
            const float* hv = g_ahF + (size_t)b * 1024;
#pragma unroll 8
            for (int j = 0; j < 32; j++) {
                int f = lane + 32 * j;
                s += wr[f] * hv[f];
            }
#pragma unroll
            for (int o = 16; o; o >>= 1) s += __shfl_down_sync(0xffffffffu, s, o);
            if (lane == 0) g_pq[b * 128 + cta] = s;
        }
        if (t > 0 && cta < 81) {
            int b = wi;
            float s = 0.f;
            const float* wrow = (cta < 80) ? (proj_w + (size_t)cta * 1536) : gate_w;
            const float* dv = g_dhF + (size_t)b * 1024;
            const float* cv = g_ctxF + (size_t)b * 512;
#pragma unroll 8
            for (int j = 0; j < 48; j++) {
                int f = lane + 32 * j;
                float xv = (f < 1024) ? dv[f] : cv[f - 1024];
                s += wrow[f] * xv;
            }
#pragma unroll
            for (int o = 16; o; o >>= 1) s += __shfl_down_sync(0xffffffffu, s, o);
            if (lane == 0) {
                if (cta < 80)
                    out[((size_t)b * NMEL + cta) * TOUT + (t - 1)] = s + proj_b[cta];
                else
                    out[GATE_OFF + (size_t)b * TOUT + (t - 1)] = s + gate_b[0];
            }
        }
        gbar(gen, cta, tid);

        if (t < TOUT) {
            // ---- Phase C: energies ----
            {
                int ts = tid >> 9, sub = tid & 511;
                int tile = cta * 2 + ts;            // (b, t-tile)
                int b = tile >> 3;
                int t0 = (tile & 7) * 32;
                bool active = (t0 < memlen[b]);
                float* scr  = ds + ts * 2048;
                float* cat  = scr;                  // [2][64]
                float* co   = scr + 128;            // [32][36] padded
                float* spq  = scr + 1280;           // [128]
                float* part = scr + 1408;           // [16][32]
                if (active) {
                    if (sub < 124) {
                        int c = sub / 62, tl = sub % 62;
                        int tg = t0 - 15 + tl;
                        float vv = 0.f;
                        if (tg >= 0 && tg < TIN) vv = (c ? g_awc : g_aw)[b * TIN + tg];
                        cat[c * 64 + tl] = vv;
                    }
                    if (sub < 128) spq[sub] = g_pq[b * 128 + sub];
                }
                __syncthreads();
                if (active) {
#pragma unroll
                    for (int j = 0; j < 2; j++) {
                        int id = sub + j * 512;
                        int tl = id >> 5, f = id & 31;
                        const float* lc = &s_lc[f * 62];
                        float s = 0.f;
#pragma unroll
                        for (int k = 0; k < 31; k++) s += lc[k] * cat[tl + k];
#pragma unroll
                        for (int k = 0; k < 31; k++) s += lc[31 + k] * cat[64 + tl + k];
                        co[tl * 36 + f] = s;
                    }
                }
                __syncthreads();
                if (active) {
                    int wa = sub >> 5, tl = sub & 31;
                    uint4 cr[8];
                    const uint4* co4 = (const uint4*)(co + tl * 36);
#pragma unroll
                    for (int k = 0; k < 8; k++) cr[k] = co4[k];
                    const float* pmb = g_pm + ((size_t)b * 128) * TIN + t0 + tl;
                    float accv = 0.f;
#pragma unroll 2
                    for (int a = wa * 8; a < wa * 8 + 8; a++) {
                        const uint4* d4 = (const uint4*)&s_dense[a * 32];
                        ull p0 = 0, p1 = 0;
#pragma unroll
                        for (int k = 0; k < 8; k++) {
                            uint4 dv = d4[k];
                            fma2(p0, pk(dv.x, dv.y), pk(cr[k].x, cr[k].y));
                            fma2(p1, pk(dv.z, dv.w), pk(cr[k].z, cr[k].w));
                        }
                        float loc = hsum(p0) + hsum(p1);
                        float pmv = pmb[(size_t)a * TIN];
                        accv += ftanh(spq[a] + pmv + loc) * __ldg(v + a);
                    }
                    part[wa * 32 + tl] = accv;
                }
                __syncthreads();
                if (sub < 32) {
                    int tg = t0 + sub;
                    float e = -1e9f;
                    if (active && tg < memlen[b]) {
                        e = 0.f;
#pragma unroll
                        for (int j = 0; j < 16; j++) e += part[j * 32 + sub];
                    }
                    g_e[b * TIN + tg] = e;
                }
            }
            gbar(gen, cta, tid);

            // ---- Phase D: softmax + context ----
            {
                int b = cta >> 2, x = cta & 3;
                float* s_wgt = ds;
                float* red   = ds + 256;
                float* bval  = ds + 266;
                float e = (tid < 256) ? g_e[b * 256 + tid] : -1e30f;
                float m = e;
#pragma unroll
                for (int o = 16; o; o >>= 1) m = fmaxf(m, __shfl_xor_sync(0xffffffffu, m, o));
                if (lane == 0 && tid < 256) red[wi] = m;
                __syncthreads();
                if (tid == 0) {
                    float mm = red[0];
#pragma unroll
                    for (int i = 1; i < 8; i++) mm = fmaxf(mm, red[i]);
                    bval[0] = mm;
                }
                __syncthreads();
                float w0 = (tid < 256) ? __expf(e - bval[0]) : 0.f;
                float ssum = w0;
#pragma unroll
                for (int o = 16; o; o >>= 1) ssum += __shfl_xor_sync(0xffffffffu, ssum, o);
                if (lane == 0 && tid < 256) red[wi] = ssum;
                __syncthreads();
                if (tid == 0) {
                    float tt2 = 0.f;
#pragma unroll
                    for (int i = 0; i < 8; i++) tt2 += red[i];
                    bval[1] = tt2;
                }
                __syncthreads();
                if (tid < 256) {
                    float wgt = w0 * __fdividef(1.f, bval[1]);
                    s_wgt[tid] = wgt;
                    if (x == 0) {
                        g_aw[b * 256 + tid] = wgt;
                        g_awc[b * 256 + tid] += wgt;
                        out[ALIGN_OFF + (size_t)(b * TOUT + t) * TIN + tid] = wgt;
                    }
                }
                __syncthreads();
                {
                    int ebase = x * 128 + wi * 4;
#pragma unroll
                    for (int i = 0; i < 4; i++) {
                        int e2 = ebase + i;
                        const float* mrow = g_memT + ((size_t)b * 512 + e2) * TIN;
                        float s = 0.f;
#pragma unroll
                        for (int j = 0; j < 8; j++) {
                            int tt3 = lane + 32 * j;
                            s += mrow[tt3] * s_wgt[tt3];
                        }
#pragma unroll
                        for (int o = 16; o; o >>= 1) s += __shfl_down_sync(0xffffffffu, s, o);
                        if (lane == 0) {
                            g_ctxF[(size_t)b * 512 + e2] = s;
                            pack_x(g_attCtx, e2 >> 4, e2 & 15, b, s);
                            pack_x(g_decCtx, e2 >> 4, e2 & 15, b, s);
                        }
                    }
                }
            }
            gbar(gen, cta, tid);
        }
    }
}

// ---------------------------------------------------------------------------
// launch: 2 graph nodes
// ---------------------------------------------------------------------------
extern "C" void kernel_launch(void* const* d_in, const int* in_sizes, int n_in,
                              void* d_out, int out_size) {
    const float* memory    = (const float*)d_in[0];
    const float* dec_in    = (const float*)d_in[1];
    const int*   memlen    = (const int*)  d_in[2];
    const float* prenet_w1 = (const float*)d_in[3];
    const float* prenet_w2 = (const float*)d_in[4];
    const float* att_wih   = (const float*)d_in[5];
    const float* att_whh   = (const float*)d_in[6];
    const float* att_b     = (const float*)d_in[7];
    const float* wq        = (const float*)d_in[8];
    const float* wm        = (const float*)d_in[9];
    const float* v         = (const float*)d_in[10];
    const float* loc_conv  = (const float*)d_in[11];
    const float* loc_dense = (const float*)d_in[12];
    const float* dec_wih   = (const float*)d_in[13];
    const float* dec_whh   = (const float*)d_in[14];
    const float* dec_b     = (const float*)d_in[15];
    const float* proj_w    = (const float*)d_in[16];
    const float* proj_b    = (const float*)d_in[17];
    const float* gate_w    = (const float*)d_in[18];
    const float* gate_b    = (const float*)d_in[19];
    float* out = (float*)d_out;

    cudaFuncSetAttribute(k_main, cudaFuncAttributeMaxDynamicSharedMemorySize, DSBYTES);

    k_reset<<<1, NBLK>>>();
    k_main<<<NBLK, NTHR, DSBYTES>>>(memory, dec_in, memlen, prenet_w1, prenet_w2,
                                    att_wih, att_whh, att_b, wq, wm, v,
                                    loc_conv, loc_dense, dec_wih, dec_whh, dec_b,
                                    proj_w, proj_b, gate_w, gate_b, out);
}